// round 15
// baseline (speedup 1.0000x reference)
#include <cuda_runtime.h>
#include <cuda_fp16.h>
#include <math.h>

#define NN 100000
#define NE 1600000
#define ET 1700000   // NE + NN self loops
#define SCAN_B 1024
#define NSCANB ((NN + SCAN_B - 1) / SCAN_B)   // 98

// GEMM tile: M=64, N=128, K=128 smem-resident fp16, pitch 136 halves
#define HP 136
#define GEMM_SMEM ((64 + 128) * HP * 2)   // 52,224 bytes

// ---------------- device scratch (no allocations allowed) ----------------
__device__ __half g_xl[(size_t)NN * 512];
__device__ __half g_xr[(size_t)NN * 512];
__device__ __half g_h[(size_t)NN * 128];
__device__ int    g_cnt[NN];
__device__ int    g_off[NN + 1];
__device__ int    g_cur[NN];
__device__ int    g_bsum[NSCANB];
__device__ int    g_srcs[ET];

__device__ __forceinline__ float lrelu02(float t) {
    return t > 0.f ? t : 0.2f * t;
}

__device__ __forceinline__ void ldsm_x4(unsigned& r0, unsigned& r1, unsigned& r2, unsigned& r3,
                                        unsigned addr) {
    asm volatile("ldmatrix.sync.aligned.m8n8.x4.shared.b16 {%0,%1,%2,%3}, [%4];"
                 : "=r"(r0), "=r"(r1), "=r"(r2), "=r"(r3) : "r"(addr));
}
__device__ __forceinline__ void ldsm_x4_t(unsigned& r0, unsigned& r1, unsigned& r2, unsigned& r3,
                                          unsigned addr) {
    asm volatile("ldmatrix.sync.aligned.m8n8.x4.trans.shared.b16 {%0,%1,%2,%3}, [%4];"
                 : "=r"(r0), "=r"(r1), "=r"(r2), "=r"(r3) : "r"(addr));
}
__device__ __forceinline__ void mma_f16(float* c,
    unsigned a0, unsigned a1, unsigned a2, unsigned a3, unsigned b0, unsigned b1)
{
    asm volatile(
        "mma.sync.aligned.m16n8k16.row.col.f32.f16.f16.f32 "
        "{%0,%1,%2,%3}, {%4,%5,%6,%7}, {%8,%9}, {%0,%1,%2,%3};"
        : "+f"(c[0]), "+f"(c[1]), "+f"(c[2]), "+f"(c[3])
        : "r"(a0), "r"(a1), "r"(a2), "r"(a3), "r"(b0), "r"(b1));
}

__device__ __forceinline__ float4 ld_h4(const __half* p, size_t idx4) {
    uint2 raw = ((const uint2*)p)[idx4];
    __half2 h0 = *(__half2*)&raw.x;
    __half2 h1 = *(__half2*)&raw.y;
    float2 f0 = __half22float2(h0);
    float2 f1 = __half22float2(h1);
    return make_float4(f0.x, f0.y, f1.x, f1.y);
}

// ================= CSR build =================
__global__ void csr_count(const int* __restrict__ edst) {
    int e = blockIdx.x * blockDim.x + threadIdx.x;
    if (e >= ET) return;
    int d = (e < NE) ? edst[e] : e - NE;
    atomicAdd(&g_cnt[d], 1);
}

__global__ __launch_bounds__(SCAN_B) void csr_scan1() {
    __shared__ int sh[SCAN_B];
    int tid = threadIdx.x;
    int i = blockIdx.x * SCAN_B + tid;
    int v = (i < NN) ? g_cnt[i] : 0;
    sh[tid] = v;
    __syncthreads();
#pragma unroll
    for (int off = 1; off < SCAN_B; off <<= 1) {
        int t = (tid >= off) ? sh[tid - off] : 0;
        __syncthreads();
        sh[tid] += t;
        __syncthreads();
    }
    if (i < NN) g_off[i] = sh[tid] - v;
    if (tid == SCAN_B - 1) g_bsum[blockIdx.x] = sh[tid];
}

__global__ void csr_scan2() {
    if (threadIdx.x == 0 && blockIdx.x == 0) {
        int run = 0;
        for (int b = 0; b < NSCANB; b++) {
            int t = g_bsum[b];
            g_bsum[b] = run;
            run += t;
        }
    }
}

__global__ void csr_scan3() {
    int i = blockIdx.x * blockDim.x + threadIdx.x;
    if (i < NN) {
        int o = g_off[i] + g_bsum[i >> 10];
        g_off[i] = o;
        g_cur[i] = o;
    }
    if (i == 0) g_off[NN] = ET;
}

__global__ void csr_scatter(const int* __restrict__ esrc, const int* __restrict__ edst) {
    int e = blockIdx.x * blockDim.x + threadIdx.x;
    if (e >= ET) return;
    int s, d;
    if (e < NE) { s = esrc[e]; d = edst[e]; } else { s = e - NE; d = s; }
    int pos = atomicAdd(&g_cur[d], 1);
    g_srcs[pos] = s;
}

// ================= fp16 MMA GEMM: K=128 smem-resident, paired Wl/Wr =======
__global__ __launch_bounds__(256) void gemm_fp16(
    const float* __restrict__ Af, const __half* __restrict__ Ah,
    const float* __restrict__ W0, const float* __restrict__ b0v, __half* __restrict__ out0,
    const float* __restrict__ W1, const float* __restrict__ b1v, __half* __restrict__ out1,
    int OUT)
{
    extern __shared__ __half sm_h[];
    __half (*As)[HP] = (__half(*)[HP])sm_h;
    __half (*Bs)[HP] = (__half(*)[HP])(sm_h + 64 * HP);

    const float* W = blockIdx.z ? W1 : W0;
    const float* bias = blockIdx.z ? b1v : b0v;
    __half* out = blockIdx.z ? out1 : out0;

    int m0 = blockIdx.x * 64, n0 = blockIdx.y * 128;
    int tid = threadIdx.x;
    int wid = tid >> 5, lane = tid & 31;
    int wm = (wid >> 2) * 32;
    int wn = (wid & 3) * 32;
    int grp = lane >> 2, tig = lane & 3;

    if (Ah) {
#pragma unroll
        for (int l = tid; l < 64 * 32; l += 256) {
            int r = l >> 5, q = l & 31;
            uint2 v = (m0 + r < NN) ? ((const uint2*)(Ah + (size_t)(m0 + r) * 128))[q]
                                    : make_uint2(0u, 0u);
            *(uint2*)&As[r][q * 4] = v;
        }
    } else {
#pragma unroll
        for (int l = tid; l < 64 * 32; l += 256) {
            int r = l >> 5, q = l & 31;
            float4 v = (m0 + r < NN) ? *(const float4*)(Af + (size_t)(m0 + r) * 128 + q * 4)
                                     : make_float4(0.f, 0.f, 0.f, 0.f);
            __half2 h01 = __floats2half2_rn(v.x, v.y);
            __half2 h23 = __floats2half2_rn(v.z, v.w);
            uint2 hh = make_uint2(*(unsigned*)&h01, *(unsigned*)&h23);
            *(uint2*)&As[r][q * 4] = hh;
        }
    }
#pragma unroll
    for (int l = tid; l < 128 * 32; l += 256) {
        int k = l >> 5, q = l & 31;
        float4 v = *(const float4*)(W + (size_t)k * OUT + n0 + q * 4);
        __half2 h01 = __floats2half2_rn(v.x, v.y);
        __half2 h23 = __floats2half2_rn(v.z, v.w);
        uint2 hh = make_uint2(*(unsigned*)&h01, *(unsigned*)&h23);
        *(uint2*)&Bs[k][q * 4] = hh;
    }
    __syncthreads();

    float acc[2][4][4];
#pragma unroll
    for (int i = 0; i < 2; i++)
#pragma unroll
        for (int j = 0; j < 4; j++)
#pragma unroll
            for (int q = 0; q < 4; q++) acc[i][j][q] = 0.f;

    int lrow = (lane & 7) + 8 * ((lane >> 3) & 1);
    int lcol8 = 8 * (lane >> 4);

#pragma unroll
    for (int ks = 0; ks < 8; ks++) {
        int k0 = ks * 16;
        unsigned af[2][4], bt[2][4];
#pragma unroll
        for (int i = 0; i < 2; i++) {
            unsigned addr = (unsigned)__cvta_generic_to_shared(
                &As[wm + i * 16 + lrow][k0 + lcol8]);
            ldsm_x4(af[i][0], af[i][1], af[i][2], af[i][3], addr);
        }
#pragma unroll
        for (int j2 = 0; j2 < 2; j2++) {
            unsigned addr = (unsigned)__cvta_generic_to_shared(
                &Bs[k0 + lrow][wn + j2 * 16 + lcol8]);
            ldsm_x4_t(bt[j2][0], bt[j2][1], bt[j2][2], bt[j2][3], addr);
        }
#pragma unroll
        for (int i = 0; i < 2; i++) {
#pragma unroll
            for (int j2 = 0; j2 < 2; j2++) {
                mma_f16(acc[i][j2 * 2 + 0], af[i][0], af[i][1], af[i][2], af[i][3],
                        bt[j2][0], bt[j2][1]);
                mma_f16(acc[i][j2 * 2 + 1], af[i][0], af[i][1], af[i][2], af[i][3],
                        bt[j2][2], bt[j2][3]);
            }
        }
    }

#pragma unroll
    for (int i = 0; i < 2; i++) {
        int r = m0 + wm + i * 16 + grp;
#pragma unroll
        for (int j = 0; j < 4; j++) {
            int col = n0 + wn + j * 8 + tig * 2;
            float2 bi = *(const float2*)(bias + col);
            if (r < NN) {
                __half2 v0 = __floats2half2_rn(acc[i][j][0] + bi.x, acc[i][j][1] + bi.y);
                *(__half2*)(out + (size_t)r * OUT + col) = v0;
            }
            if (r + 8 < NN) {
                __half2 v1 = __floats2half2_rn(acc[i][j][2] + bi.x, acc[i][j][3] + bi.y);
                *(__half2*)(out + (size_t)(r + 8) * OUT + col) = v1;
            }
        }
    }
}

// ================= fused edge phase: 2 warps per dst node =================
__device__ __forceinline__ float edge_p32(const float4& a, const float4& b, const float4& w) {
    float t, part = 0.f;
    t = lrelu02(a.x + b.x); part += w.x * t;
    t = lrelu02(a.y + b.y); part += w.y * t;
    t = lrelu02(a.z + b.z); part += w.z * t;
    t = lrelu02(a.w + b.w); part += w.w * t;
    part += __shfl_xor_sync(0xffffffffu, part, 1);
    part += __shfl_xor_sync(0xffffffffu, part, 2);
    part += __shfl_xor_sync(0xffffffffu, part, 4);
    return __expf(part);
}

// 8 warps/block = 4 nodes x 2 sub-warps. NN % 4 == 0 -> no guards.
__global__ __launch_bounds__(256) void fused_edge32(
    const __half* __restrict__ xl, const __half* __restrict__ xr,
    const float* __restrict__ att, const float* __restrict__ bias,
    __half* __restrict__ hout)
{
    __shared__ float sm[4][2][160];   // per node-sub: acc[128] + den[32]

    int tid = threadIdx.x;
    int wid = tid >> 5, lane = tid & 31;
    int n = wid >> 1, sub = wid & 1;
    int d = blockIdx.x * 4 + n;

    float4 b = ld_h4(xr, (size_t)d * 32 + lane);
    float4 w = ((const float4*)att)[lane];

    float den0 = 0.f, den1 = 0.f;
    float4 acc0 = {0.f, 0.f, 0.f, 0.f}, acc1 = {0.f, 0.f, 0.f, 0.f};

    int i0 = g_off[d] + sub, i1 = g_off[d + 1];
    int i = i0;
    for (; i + 2 < i1; i += 4) {           // this warp: every other edge, unroll 2
        int s0 = g_srcs[i], s1 = g_srcs[i + 2];
        float4 a0 = ld_h4(xl, (size_t)s0 * 32 + lane);
        float4 a1 = ld_h4(xl, (size_t)s1 * 32 + lane);
        float p0 = edge_p32(a0, b, w);
        float p1 = edge_p32(a1, b, w);
        acc0.x += p0 * a0.x; acc0.y += p0 * a0.y; acc0.z += p0 * a0.z; acc0.w += p0 * a0.w;
        den0 += p0;
        acc1.x += p1 * a1.x; acc1.y += p1 * a1.y; acc1.z += p1 * a1.z; acc1.w += p1 * a1.w;
        den1 += p1;
    }
    for (; i < i1; i += 2) {
        int s = g_srcs[i];
        float4 a = ld_h4(xl, (size_t)s * 32 + lane);
        float p = edge_p32(a, b, w);
        acc0.x += p * a.x; acc0.y += p * a.y; acc0.z += p * a.z; acc0.w += p * a.w;
        den0 += p;
    }

    float den = den0 + den1;
    float4 acc;
    acc.x = acc0.x + acc1.x;
    acc.y = acc0.y + acc1.y;
    acc.z = acc0.z + acc1.z;
    acc.w = acc0.w + acc1.w;

    // merge the two sub-warps through smem
    float* mine = sm[n][sub];
    *(float4*)&mine[lane * 4] = acc;
    mine[128 + lane] = den;
    __syncthreads();

    if (sub == 0) {
        const float* oth = sm[n][1];
        float4 oa = *(const float4*)&oth[lane * 4];
        acc.x += oa.x; acc.y += oa.y; acc.z += oa.z; acc.w += oa.w;
        den += oth[128 + lane];

        float inv = 1.f / den;
        const float4 bi = ((const float4*)bias)[lane];
        float4 r;
        r.x = acc.x * inv + bi.x;
        r.y = acc.y * inv + bi.y;
        r.z = acc.z * inv + bi.z;
        r.w = acc.w * inv + bi.w;
        r.x = r.x > 0.f ? r.x : (__expf(r.x) - 1.f);
        r.y = r.y > 0.f ? r.y : (__expf(r.y) - 1.f);
        r.z = r.z > 0.f ? r.z : (__expf(r.z) - 1.f);
        r.w = r.w > 0.f ? r.w : (__expf(r.w) - 1.f);
        __half2 h0 = __floats2half2_rn(r.x, r.y);
        __half2 h1 = __floats2half2_rn(r.z, r.w);
        uint2 hh = make_uint2(*(unsigned*)&h0, *(unsigned*)&h1);
        ((uint2*)hout)[(size_t)d * 32 + lane] = hh;
    }
}

__device__ __forceinline__ float edge_p128(const float4* a, const float4* b, const float4* w) {
    float part = 0.f;
#pragma unroll
    for (int j = 0; j < 4; j++) {
        float t;
        t = lrelu02(a[j].x + b[j].x); part += w[j].x * t;
        t = lrelu02(a[j].y + b[j].y); part += w[j].y * t;
        t = lrelu02(a[j].z + b[j].z); part += w[j].z * t;
        t = lrelu02(a[j].w + b[j].w); part += w[j].w * t;
    }
    part += __shfl_xor_sync(0xffffffffu, part, 1);
    part += __shfl_xor_sync(0xffffffffu, part, 2);
    part += __shfl_xor_sync(0xffffffffu, part, 4);
    return __expf(part);
}

// 8 warps/block = 4 nodes x 2 sub-warps; head h = lane>>3, g = lane&7.
__global__ __launch_bounds__(256) void fused_edge128(
    const __half* __restrict__ xl, const __half* __restrict__ xr,
    const float* __restrict__ att, const float* __restrict__ bias,
    float* __restrict__ out)
{
    __shared__ float sm[4][2][544];   // per node-sub: acc[512] + den[32]

    int tid = threadIdx.x;
    int wid = tid >> 5, lane = tid & 31;
    int n = wid >> 1, sub = wid & 1;
    int d = blockIdx.x * 4 + n;
    int h = lane >> 3, g = lane & 7;
    int base = h * 32 + g * 4;

    float4 b[4], w[4];
#pragma unroll
    for (int j = 0; j < 4; j++) {
        b[j] = ld_h4(xr, (size_t)d * 128 + base + j);
        w[j] = ((const float4*)att)[base + j];
    }
    float den = 0.f;
    float4 acc[4];
#pragma unroll
    for (int j = 0; j < 4; j++) acc[j] = make_float4(0.f, 0.f, 0.f, 0.f);

    int i0 = g_off[d] + sub, i1 = g_off[d + 1];
    int i = i0;
    for (; i + 2 < i1; i += 4) {
        int s0 = g_srcs[i], s1 = g_srcs[i + 2];
        float4 a0[4], a1[4];
#pragma unroll
        for (int j = 0; j < 4; j++) {
            a0[j] = ld_h4(xl, (size_t)s0 * 128 + base + j);
            a1[j] = ld_h4(xl, (size_t)s1 * 128 + base + j);
        }
        float p0 = edge_p128(a0, b, w);
        float p1 = edge_p128(a1, b, w);
#pragma unroll
        for (int j = 0; j < 4; j++) {
            acc[j].x += p0 * a0[j].x + p1 * a1[j].x;
            acc[j].y += p0 * a0[j].y + p1 * a1[j].y;
            acc[j].z += p0 * a0[j].z + p1 * a1[j].z;
            acc[j].w += p0 * a0[j].w + p1 * a1[j].w;
        }
        den += p0 + p1;
    }
    for (; i < i1; i += 2) {
        int s = g_srcs[i];
        float4 a[4];
#pragma unroll
        for (int j = 0; j < 4; j++)
            a[j] = ld_h4(xl, (size_t)s * 128 + base + j);
        float p = edge_p128(a, b, w);
#pragma unroll
        for (int j = 0; j < 4; j++) {
            acc[j].x += p * a[j].x; acc[j].y += p * a[j].y;
            acc[j].z += p * a[j].z; acc[j].w += p * a[j].w;
        }
        den += p;
    }

    // merge the two sub-warps through smem
    float* mine = sm[n][sub];
#pragma unroll
    for (int j = 0; j < 4; j++)
        *(float4*)&mine[lane * 16 + j * 4] = acc[j];
    mine[512 + lane] = den;
    __syncthreads();

    if (sub == 0) {
        const float* oth = sm[n][1];
#pragma unroll
        for (int j = 0; j < 4; j++) {
            float4 oa = *(const float4*)&oth[lane * 16 + j * 4];
            acc[j].x += oa.x; acc[j].y += oa.y; acc[j].z += oa.z; acc[j].w += oa.w;
        }
        den += oth[512 + lane];

        float inv = 1.f / den;
        float4 accm[4];
#pragma unroll
        for (int j = 0; j < 4; j++) {
            accm[j].x = acc[j].x * inv;
            accm[j].y = acc[j].y * inv;
            accm[j].z = acc[j].z * inv;
            accm[j].w = acc[j].w * inv;
        }
        // sum across heads within the sub0 warp (full warp active)
#pragma unroll
        for (int j = 0; j < 4; j++) {
            accm[j].x += __shfl_xor_sync(0xffffffffu, accm[j].x, 8);
            accm[j].y += __shfl_xor_sync(0xffffffffu, accm[j].y, 8);
            accm[j].z += __shfl_xor_sync(0xffffffffu, accm[j].z, 8);
            accm[j].w += __shfl_xor_sync(0xffffffffu, accm[j].w, 8);
            accm[j].x += __shfl_xor_sync(0xffffffffu, accm[j].x, 16);
            accm[j].y += __shfl_xor_sync(0xffffffffu, accm[j].y, 16);
            accm[j].z += __shfl_xor_sync(0xffffffffu, accm[j].z, 16);
            accm[j].w += __shfl_xor_sync(0xffffffffu, accm[j].w, 16);
        }
        const float4 bi = ((const float4*)bias)[g * 4 + h];
        float4 r;
        r.x = 0.25f * accm[h].x + bi.x;
        r.y = 0.25f * accm[h].y + bi.y;
        r.z = 0.25f * accm[h].z + bi.z;
        r.w = 0.25f * accm[h].w + bi.w;
        ((float4*)out)[(size_t)d * 32 + g * 4 + h] = r;
    }
}

// ================= launch =================
extern "C" void kernel_launch(void* const* d_in, const int* in_sizes, int n_in,
                              void* d_out, int out_size)
{
    (void)in_sizes; (void)n_in; (void)out_size;
    const float* x = (const float*)d_in[0];
    const int* ei = (const int*)d_in[1];
    const int* esrc = ei;
    const int* edst = ei + NE;
    const float* Wl[3]   = {(const float*)d_in[2],  (const float*)d_in[8],  (const float*)d_in[14]};
    const float* bl[3]   = {(const float*)d_in[3],  (const float*)d_in[9],  (const float*)d_in[15]};
    const float* Wr[3]   = {(const float*)d_in[4],  (const float*)d_in[10], (const float*)d_in[16]};
    const float* br[3]   = {(const float*)d_in[5],  (const float*)d_in[11], (const float*)d_in[17]};
    const float* att[3]  = {(const float*)d_in[6],  (const float*)d_in[12], (const float*)d_in[18]};
    const float* bias[3] = {(const float*)d_in[7],  (const float*)d_in[13], (const float*)d_in[19]};

    __half *p_xl, *p_xr, *p_h;
    int *p_cnt;
    cudaGetSymbolAddress((void**)&p_xl, g_xl);
    cudaGetSymbolAddress((void**)&p_xr, g_xr);
    cudaGetSymbolAddress((void**)&p_h, g_h);
    cudaGetSymbolAddress((void**)&p_cnt, g_cnt);

    cudaFuncSetAttribute(gemm_fp16,
                         cudaFuncAttributeMaxDynamicSharedMemorySize, GEMM_SMEM);

    // ---- fork: CSR build on side stream, gemm L0 on main stream ----
    cudaStream_t s;
    cudaStreamCreateWithFlags(&s, cudaStreamNonBlocking);
    cudaEvent_t e0, e1;
    cudaEventCreateWithFlags(&e0, cudaEventDisableTiming);
    cudaEventCreateWithFlags(&e1, cudaEventDisableTiming);

    cudaEventRecord(e0, 0);
    cudaStreamWaitEvent(s, e0, 0);
    cudaMemsetAsync(p_cnt, 0, NN * sizeof(int), s);
    csr_count<<<(ET + 255) / 256, 256, 0, s>>>(edst);
    csr_scan1<<<NSCANB, SCAN_B, 0, s>>>();
    csr_scan2<<<1, 32, 0, s>>>();
    csr_scan3<<<(NN + 255) / 256, 256, 0, s>>>();
    csr_scatter<<<(ET + 255) / 256, 256, 0, s>>>(esrc, edst);
    cudaEventRecord(e1, s);

    // ---- layers (main/capture stream) ----
    for (int L = 0; L < 3; L++) {
        int OUT = (L == 2) ? 512 : 128;
        dim3 gg((NN + 63) / 64, OUT / 128, 2);
        if (L == 0)
            gemm_fp16<<<gg, 256, GEMM_SMEM>>>(x, nullptr, Wl[L], bl[L], p_xl,
                                              Wr[L], br[L], p_xr, OUT);
        else
            gemm_fp16<<<gg, 256, GEMM_SMEM>>>(nullptr, p_h, Wl[L], bl[L], p_xl,
                                              Wr[L], br[L], p_xr, OUT);

        if (L == 0)
            cudaStreamWaitEvent(0, e1, 0);   // join: edge phase needs the CSR

        int blocks = NN / 4;   // 4 nodes per block, 2 warps per node
        if (L < 2)
            fused_edge32<<<blocks, 256>>>(p_xl, p_xr, att[L], bias[L], p_h);
        else
            fused_edge128<<<blocks, 256>>>(p_xl, p_xr, att[L], bias[L], (float*)d_out);
    }
}